// round 1
// baseline (speedup 1.0000x reference)
#include <cuda_runtime.h>
#include <cstdint>

#define NNODE 8192
#define NEDGE 262144
#define DIN   512
#define H1D   256
#define LATD  128

// ---------------- scratch (device globals; no allocations allowed) ----------
__device__ int   g_cnt[NNODE];
__device__ int   g_start[NNODE + 1];
__device__ int   g_cursor[NNODE];
__device__ float g_dis[NNODE];
__device__ int   g_src[NEDGE];
__device__ float g_nrm[NEDGE];
__device__ float g_h1[NNODE * H1D];
__device__ float g_z1[NNODE * H1D];
__device__ float g_h2[NNODE * LATD];
__device__ float g_z2[NNODE * LATD];
__device__ int   g_is64;

// ---------------- edge dtype detection --------------------------------------
// If edge_index is int64 (little-endian, values < 8192), every odd 32-bit word
// of the first 512 words is zero. For int32 data those words are node ids
// (P(all zero) ~ 8192^-256).
__global__ void detect_k(const int* __restrict__ w) {
    int t = threadIdx.x;  // 256 threads
    int z = (w[2 * t + 1] == 0) ? 1 : 0;
    unsigned m = __ballot_sync(0xffffffffu, z);
    __shared__ int allz[8];
    if ((t & 31) == 0) allz[t >> 5] = (m == 0xffffffffu) ? 1 : 0;
    __syncthreads();
    if (t == 0) {
        int a = 1;
        #pragma unroll
        for (int i = 0; i < 8; i++) a &= allz[i];
        g_is64 = a;
    }
}

__device__ __forceinline__ int edge_at(const void* ei, int idx) {
    if (g_is64) return (int)((const long long*)ei)[idx];
    return ((const int*)ei)[idx];
}

// ---------------- CSR build --------------------------------------------------
__global__ void zero_cnt_k() {
    int i = blockIdx.x * blockDim.x + threadIdx.x;
    if (i < NNODE) g_cnt[i] = 0;
}

__global__ void count_k(const void* __restrict__ ei) {
    int e = blockIdx.x * blockDim.x + threadIdx.x;
    if (e >= NEDGE) return;
    int c = edge_at(ei, NEDGE + e);
    atomicAdd(&g_cnt[c], 1);
}

// single-block scan over 8192 counts; also computes dis = (deg+2)^-1/2
__global__ void scan_k() {
    __shared__ int part[1024];
    int t = threadIdx.x;
    int loc[8];
    int s = 0;
    #pragma unroll
    for (int i = 0; i < 8; i++) { loc[i] = g_cnt[t * 8 + i]; s += loc[i]; }
    part[t] = s;
    __syncthreads();
    for (int off = 1; off < 1024; off <<= 1) {
        int v = (t >= off) ? part[t - off] : 0;
        __syncthreads();
        part[t] += v;
        __syncthreads();
    }
    int run = part[t] - s;  // exclusive prefix
    #pragma unroll
    for (int i = 0; i < 8; i++) {
        int idx = t * 8 + i;
        g_start[idx]  = run;
        g_cursor[idx] = run;
        g_dis[idx] = rsqrtf((float)(loc[i] + 2));
        run += loc[i];
    }
    if (t == 1023) g_start[NNODE] = run;
}

__global__ void fill_k(const void* __restrict__ ei) {
    int e = blockIdx.x * blockDim.x + threadIdx.x;
    if (e >= NEDGE) return;
    int r = edge_at(ei, e);
    int c = edge_at(ei, NEDGE + e);
    int p = atomicAdd(&g_cursor[c], 1);
    g_src[p] = r;
    g_nrm[p] = g_dis[r] * g_dis[c];
}

// ---------------- generic tiled SGEMM (64x64, 4x4/thread) --------------------
// C[M,N] = op(A[M,K]) @ B[K,N] (+ bias), row-major, M%64==0, N%64==0, K%16==0
template <bool RELU_A, bool ADD_BIAS>
__global__ __launch_bounds__(256) void sgemm_k(
    const float* __restrict__ A, const float* __restrict__ B,
    const float* __restrict__ bias, float* __restrict__ C,
    int M, int N, int K)
{
    __shared__ float As[16][64];
    __shared__ float Bs[16][64];
    int tid = threadIdx.x;
    int tx = tid & 15, ty = tid >> 4;
    int brow = blockIdx.y * 64, bcol = blockIdx.x * 64;
    int ar = tid >> 2;          // 0..63
    int ac = (tid & 3) * 4;     // 0,4,8,12
    int br = tid >> 4;          // 0..15
    int bc = (tid & 15) * 4;    // 0..60
    float acc[4][4] = {};

    for (int k0 = 0; k0 < K; k0 += 16) {
        float4 av = *(const float4*)&A[(size_t)(brow + ar) * K + k0 + ac];
        if (RELU_A) {
            av.x = fmaxf(av.x, 0.f); av.y = fmaxf(av.y, 0.f);
            av.z = fmaxf(av.z, 0.f); av.w = fmaxf(av.w, 0.f);
        }
        As[ac + 0][ar] = av.x; As[ac + 1][ar] = av.y;
        As[ac + 2][ar] = av.z; As[ac + 3][ar] = av.w;
        float4 bv = *(const float4*)&B[(size_t)(k0 + br) * N + bcol + bc];
        *(float4*)&Bs[br][bc] = bv;
        __syncthreads();
        #pragma unroll
        for (int kk = 0; kk < 16; kk++) {
            float a[4], b[4];
            *(float4*)&a[0] = *(const float4*)&As[kk][ty * 4];
            *(float4*)&b[0] = *(const float4*)&Bs[kk][tx * 4];
            #pragma unroll
            for (int i = 0; i < 4; i++)
                #pragma unroll
                for (int j = 0; j < 4; j++)
                    acc[i][j] += a[i] * b[j];
        }
        __syncthreads();
    }

    float b4x = 0.f, b4y = 0.f, b4z = 0.f, b4w = 0.f;
    if (ADD_BIAS) {
        float4 b4 = *(const float4*)&bias[bcol + tx * 4];
        b4x = b4.x; b4y = b4.y; b4z = b4.z; b4w = b4.w;
    }
    #pragma unroll
    for (int i = 0; i < 4; i++) {
        float4 o;
        o.x = acc[i][0] + b4x; o.y = acc[i][1] + b4y;
        o.z = acc[i][2] + b4z; o.w = acc[i][3] + b4w;
        *(float4*)&C[(size_t)(brow + ty * 4 + i) * N + bcol + tx * 4] = o;
    }
}

// ---------------- CSR aggregation (no atomics) -------------------------------
// out[v] = sum_{e in-edges of v} nrm[e]*h[src[e]] + 2*dis[v]^2*h[v] + bias
template <int D>
__global__ __launch_bounds__(256) void agg_k(
    const float* __restrict__ h, const float* __restrict__ bias,
    float* __restrict__ out)
{
    const int TPN = D / 4;          // threads per node (float4 lanes)
    const int NPB = 256 / TPN;      // nodes per block
    int node = blockIdx.x * NPB + threadIdx.x / TPN;
    int lane = threadIdx.x % TPN;
    const float4* h4 = (const float4*)h;

    int s = g_start[node];
    int e = g_start[node + 1];
    float dv = g_dis[node];
    float self = 2.f * dv * dv;

    float4 hv = h4[(size_t)node * TPN + lane];
    float4 acc;
    acc.x = hv.x * self; acc.y = hv.y * self;
    acc.z = hv.z * self; acc.w = hv.w * self;

    for (int i = s; i < e; i++) {
        int r = g_src[i];
        float nm = g_nrm[i];
        float4 v = h4[(size_t)r * TPN + lane];
        acc.x += nm * v.x; acc.y += nm * v.y;
        acc.z += nm * v.z; acc.w += nm * v.w;
    }
    float4 b4 = ((const float4*)bias)[lane];
    acc.x += b4.x; acc.y += b4.y; acc.z += b4.z; acc.w += b4.w;
    ((float4*)out)[(size_t)node * TPN + lane] = acc;
}

// ---------------- adj = sigmoid(mu @ mu^T), symmetric ------------------------
__device__ __forceinline__ float sigf(float x) {
    return 1.f / (1.f + __expf(-x));
}

// 128x128 tile, 8x8 per thread (cols/rows split as base and base+64 to keep
// LDS.128 conflict-free within quarter-warps). Only bj>=bi tiles computed;
// mirror written via register-transpose float4 stores (64B contiguous runs).
__global__ __launch_bounds__(256, 2) void adj_k(
    const float* __restrict__ mu, float* __restrict__ out)
{
    int bi = blockIdx.y, bj = blockIdx.x;
    if (bj < bi) return;
    __shared__ float As[16][128];
    __shared__ float Bs[16][128];
    int tid = threadIdx.x;
    int tx = tid & 15, ty = tid >> 4;
    int r0 = bi * 128, c0 = bj * 128;
    float acc[8][8] = {};

    for (int k0 = 0; k0 < LATD; k0 += 16) {
        #pragma unroll
        for (int l = 0; l < 2; l++) {
            int idx = tid + l * 256;
            int ar = idx >> 2;
            int ac = (idx & 3) * 4;
            float4 av = *(const float4*)&mu[(size_t)(r0 + ar) * LATD + k0 + ac];
            As[ac + 0][ar] = av.x; As[ac + 1][ar] = av.y;
            As[ac + 2][ar] = av.z; As[ac + 3][ar] = av.w;
            float4 bv = *(const float4*)&mu[(size_t)(c0 + ar) * LATD + k0 + ac];
            Bs[ac + 0][ar] = bv.x; Bs[ac + 1][ar] = bv.y;
            Bs[ac + 2][ar] = bv.z; Bs[ac + 3][ar] = bv.w;
        }
        __syncthreads();
        #pragma unroll
        for (int kk = 0; kk < 16; kk++) {
            float a[8], b[8];
            *(float4*)&a[0] = *(const float4*)&As[kk][ty * 4];
            *(float4*)&a[4] = *(const float4*)&As[kk][64 + ty * 4];
            *(float4*)&b[0] = *(const float4*)&Bs[kk][tx * 4];
            *(float4*)&b[4] = *(const float4*)&Bs[kk][64 + tx * 4];
            #pragma unroll
            for (int i = 0; i < 8; i++)
                #pragma unroll
                for (int j = 0; j < 8; j++)
                    acc[i][j] += a[i] * b[j];
        }
        __syncthreads();
    }

    #pragma unroll
    for (int i = 0; i < 8; i++)
        #pragma unroll
        for (int j = 0; j < 8; j++)
            acc[i][j] = sigf(acc[i][j]);

    // row indices for this thread: ty*4+i (i<4) and 64+ty*4+(i-4)
    // col indices: tx*4+j (j<4) and 64+tx*4+(j-4)
    #pragma unroll
    for (int ih = 0; ih < 2; ih++) {
        int rbase = r0 + ih * 64 + ty * 4;
        #pragma unroll
        for (int i = 0; i < 4; i++) {
            float4 o1, o2;
            o1.x = acc[ih * 4 + i][0]; o1.y = acc[ih * 4 + i][1];
            o1.z = acc[ih * 4 + i][2]; o1.w = acc[ih * 4 + i][3];
            o2.x = acc[ih * 4 + i][4]; o2.y = acc[ih * 4 + i][5];
            o2.z = acc[ih * 4 + i][6]; o2.w = acc[ih * 4 + i][7];
            size_t row = (size_t)(rbase + i) * NNODE;
            *(float4*)&out[row + c0 + tx * 4]      = o1;
            *(float4*)&out[row + c0 + 64 + tx * 4] = o2;
        }
    }

    if (bj > bi) {  // mirror tile (diagonal tiles are already fully written)
        #pragma unroll
        for (int jh = 0; jh < 2; jh++) {
            int cbase = c0 + jh * 64 + tx * 4;
            #pragma unroll
            for (int j = 0; j < 4; j++) {
                int jj = jh * 4 + j;
                float4 t1, t2;
                t1.x = acc[0][jj]; t1.y = acc[1][jj];
                t1.z = acc[2][jj]; t1.w = acc[3][jj];
                t2.x = acc[4][jj]; t2.y = acc[5][jj];
                t2.z = acc[6][jj]; t2.w = acc[7][jj];
                size_t row = (size_t)(cbase + j) * NNODE;
                *(float4*)&out[row + r0 + ty * 4]      = t1;
                *(float4*)&out[row + r0 + 64 + ty * 4] = t2;
            }
        }
    }
}

// ---------------- launch -----------------------------------------------------
extern "C" void kernel_launch(void* const* d_in, const int* in_sizes, int n_in,
                              void* d_out, int out_size)
{
    const float* x   = (const float*)d_in[0];
    const void*  ei  = d_in[1];
    const float* W1  = (const float*)d_in[2];
    const float* b1  = (const float*)d_in[3];
    const float* W2  = (const float*)d_in[4];
    const float* b2  = (const float*)d_in[5];
    const float* Wmu = (const float*)d_in[6];
    const float* bmu = (const float*)d_in[7];
    const float* Wlv = (const float*)d_in[8];
    const float* blv = (const float*)d_in[9];

    float* out = (float*)d_out;                       // adj [N,N]
    float* mu  = out + (size_t)NNODE * NNODE;         // mu  [N,LAT]
    float* lv  = mu + (size_t)NNODE * LATD;           // logvar [N,LAT]

    float *d_h1, *d_z1, *d_h2, *d_z2;
    cudaGetSymbolAddress((void**)&d_h1, g_h1);
    cudaGetSymbolAddress((void**)&d_z1, g_z1);
    cudaGetSymbolAddress((void**)&d_h2, g_h2);
    cudaGetSymbolAddress((void**)&d_z2, g_z2);

    // graph structure
    detect_k<<<1, 256>>>((const int*)ei);
    zero_cnt_k<<<NNODE / 256, 256>>>();
    count_k<<<NEDGE / 256, 256>>>(ei);
    scan_k<<<1, 1024>>>();
    fill_k<<<NEDGE / 256, 256>>>(ei);

    // GCN layer 1: h1 = x @ W1 ; z1 = agg(h1) + b1
    sgemm_k<false, false><<<dim3(H1D / 64, NNODE / 64), 256>>>(
        x, W1, nullptr, d_h1, NNODE, H1D, DIN);
    agg_k<H1D><<<NNODE / 4, 256>>>(d_h1, b1, d_z1);

    // GCN layer 2: h2 = relu(z1) @ W2 ; z2 = agg(h2) + b2
    sgemm_k<true, false><<<dim3(LATD / 64, NNODE / 64), 256>>>(
        d_z1, W2, nullptr, d_h2, NNODE, LATD, H1D);
    agg_k<LATD><<<NNODE / 8, 256>>>(d_h2, b2, d_z2);

    // heads
    sgemm_k<false, true><<<dim3(LATD / 64, NNODE / 64), 256>>>(
        d_z2, Wmu, bmu, mu, NNODE, LATD, LATD);
    sgemm_k<false, true><<<dim3(LATD / 64, NNODE / 64), 256>>>(
        d_z2, Wlv, blv, lv, NNODE, LATD, LATD);

    // adj = sigmoid(mu @ mu^T)
    adj_k<<<dim3(NNODE / 128, NNODE / 128), 256>>>(mu, out);
}

// round 2
// speedup vs baseline: 1.5066x; 1.5066x over previous
#include <cuda_runtime.h>
#include <cstdint>

#define NNODE 8192
#define NEDGE 262144
#define DIN   512
#define H1D   256
#define LATD  128

// ---------------- scratch (device globals; no allocations allowed) ----------
__device__ int   g_cnt[NNODE];
__device__ int   g_start[NNODE + 1];
__device__ int   g_cursor[NNODE];
__device__ float g_dis[NNODE];
__device__ int   g_src[NEDGE];
__device__ float g_nrm[NEDGE];
__device__ float g_h1[NNODE * H1D];
__device__ float g_z1[NNODE * H1D];
__device__ float g_h2[NNODE * LATD];
__device__ float g_z2[NNODE * LATD];
__device__ int   g_is64;

// ---------------- edge dtype detection --------------------------------------
__global__ void detect_k(const int* __restrict__ w) {
    int t = threadIdx.x;  // 256 threads
    int z = (w[2 * t + 1] == 0) ? 1 : 0;
    unsigned m = __ballot_sync(0xffffffffu, z);
    __shared__ int allz[8];
    if ((t & 31) == 0) allz[t >> 5] = (m == 0xffffffffu) ? 1 : 0;
    __syncthreads();
    if (t == 0) {
        int a = 1;
        #pragma unroll
        for (int i = 0; i < 8; i++) a &= allz[i];
        g_is64 = a;
    }
}

__device__ __forceinline__ int edge_at(const void* ei, int idx) {
    if (g_is64) return (int)((const long long*)ei)[idx];
    return ((const int*)ei)[idx];
}

// ---------------- CSR build --------------------------------------------------
__global__ void zero_cnt_k() {
    int i = blockIdx.x * blockDim.x + threadIdx.x;
    if (i < NNODE) g_cnt[i] = 0;
}

__global__ void count_k(const void* __restrict__ ei) {
    int e = blockIdx.x * blockDim.x + threadIdx.x;
    if (e >= NEDGE) return;
    int c = edge_at(ei, NEDGE + e);
    atomicAdd(&g_cnt[c], 1);
}

// warp-shuffle scan over 8192 counts; also computes dis = (deg+2)^-1/2
__global__ void scan_k() {
    __shared__ int wsum[32];
    int t = threadIdx.x;         // 1024 threads
    int lane = t & 31, w = t >> 5;
    int loc[8];
    int s = 0;
    #pragma unroll
    for (int i = 0; i < 8; i++) { loc[i] = g_cnt[t * 8 + i]; s += loc[i]; }
    // inclusive warp scan of per-thread sums
    int v = s;
    #pragma unroll
    for (int off = 1; off < 32; off <<= 1) {
        int u = __shfl_up_sync(0xffffffffu, v, off);
        if (lane >= off) v += u;
    }
    if (lane == 31) wsum[w] = v;
    __syncthreads();
    if (w == 0) {
        int x = wsum[lane];
        #pragma unroll
        for (int off = 1; off < 32; off <<= 1) {
            int u = __shfl_up_sync(0xffffffffu, x, off);
            if (lane >= off) x += u;
        }
        wsum[lane] = x;
    }
    __syncthreads();
    int run = (w ? wsum[w - 1] : 0) + (v - s);   // exclusive prefix
    #pragma unroll
    for (int i = 0; i < 8; i++) {
        int idx = t * 8 + i;
        g_start[idx]  = run;
        g_cursor[idx] = run;
        g_dis[idx] = rsqrtf((float)(loc[i] + 2));
        run += loc[i];
    }
    if (t == 1023) g_start[NNODE] = run;
}

__global__ void fill_k(const void* __restrict__ ei) {
    int e = blockIdx.x * blockDim.x + threadIdx.x;
    if (e >= NEDGE) return;
    int r = edge_at(ei, e);
    int c = edge_at(ei, NEDGE + e);
    int p = atomicAdd(&g_cursor[c], 1);
    g_src[p] = r;
    g_nrm[p] = g_dis[r] * g_dis[c];
}

// ---------------- fp32 SGEMM, 128x128 tile, 8x8 per thread -------------------
// C[M,N] = op(A[M,K]) @ B[K,N] (+ bias); M%128==0, N%128==0, K%16==0
template <bool RELU_A, bool ADD_BIAS>
__global__ __launch_bounds__(256, 2) void sgemm128_k(
    const float* __restrict__ A, const float* __restrict__ B,
    const float* __restrict__ bias, float* __restrict__ C,
    int M, int N, int K)
{
    __shared__ float As[16][132];
    __shared__ float Bs[16][132];
    int tid = threadIdx.x;
    int tx = tid & 15, ty = tid >> 4;
    int r0 = blockIdx.y * 128, c0 = blockIdx.x * 128;
    float acc[8][8] = {};

    for (int k0 = 0; k0 < K; k0 += 16) {
        #pragma unroll
        for (int l = 0; l < 2; l++) {
            int idx = tid + l * 256;              // 0..511
            int m  = idx >> 2;                    // 0..127
            int kc = (idx & 3) * 4;               // 0,4,8,12
            float4 va = *(const float4*)&A[(size_t)(r0 + m) * K + k0 + kc];
            if (RELU_A) {
                va.x = fmaxf(va.x, 0.f); va.y = fmaxf(va.y, 0.f);
                va.z = fmaxf(va.z, 0.f); va.w = fmaxf(va.w, 0.f);
            }
            As[kc + 0][m] = va.x; As[kc + 1][m] = va.y;
            As[kc + 2][m] = va.z; As[kc + 3][m] = va.w;
            int br = idx >> 5;                    // 0..15
            int bc = (idx & 31) * 4;              // 0..124
            *(float4*)&Bs[br][bc] = *(const float4*)&B[(size_t)(k0 + br) * N + c0 + bc];
        }
        __syncthreads();
        #pragma unroll
        for (int kk = 0; kk < 16; kk++) {
            float a[8], b[8];
            *(float4*)&a[0] = *(const float4*)&As[kk][ty * 4];
            *(float4*)&a[4] = *(const float4*)&As[kk][64 + ty * 4];
            *(float4*)&b[0] = *(const float4*)&Bs[kk][tx * 4];
            *(float4*)&b[4] = *(const float4*)&Bs[kk][64 + tx * 4];
            #pragma unroll
            for (int i = 0; i < 8; i++)
                #pragma unroll
                for (int j = 0; j < 8; j++)
                    acc[i][j] += a[i] * b[j];
        }
        __syncthreads();
    }

    float bl[8] = {};
    if (ADD_BIAS) {
        *(float4*)&bl[0] = *(const float4*)&bias[c0 + tx * 4];
        *(float4*)&bl[4] = *(const float4*)&bias[c0 + 64 + tx * 4];
    }
    #pragma unroll
    for (int ih = 0; ih < 2; ih++) {
        #pragma unroll
        for (int i = 0; i < 4; i++) {
            int r = r0 + ih * 64 + ty * 4 + i;
            float4 o1, o2;
            o1.x = acc[ih * 4 + i][0] + bl[0]; o1.y = acc[ih * 4 + i][1] + bl[1];
            o1.z = acc[ih * 4 + i][2] + bl[2]; o1.w = acc[ih * 4 + i][3] + bl[3];
            o2.x = acc[ih * 4 + i][4] + bl[4]; o2.y = acc[ih * 4 + i][5] + bl[5];
            o2.z = acc[ih * 4 + i][6] + bl[6]; o2.w = acc[ih * 4 + i][7] + bl[7];
            *(float4*)&C[(size_t)r * N + c0 + tx * 4]      = o1;
            *(float4*)&C[(size_t)r * N + c0 + 64 + tx * 4] = o2;
        }
    }
}

// ---------------- CSR aggregation (no atomics) -------------------------------
template <int D>
__global__ __launch_bounds__(256) void agg_k(
    const float* __restrict__ h, const float* __restrict__ bias,
    float* __restrict__ out)
{
    const int TPN = D / 4;
    const int NPB = 256 / TPN;
    int node = blockIdx.x * NPB + threadIdx.x / TPN;
    int lane = threadIdx.x % TPN;
    const float4* h4 = (const float4*)h;

    int s = g_start[node];
    int e = g_start[node + 1];
    float dv = g_dis[node];
    float self = 2.f * dv * dv;

    float4 hv = h4[(size_t)node * TPN + lane];
    float4 acc;
    acc.x = hv.x * self; acc.y = hv.y * self;
    acc.z = hv.z * self; acc.w = hv.w * self;

    for (int i = s; i < e; i++) {
        int r = g_src[i];
        float nm = g_nrm[i];
        float4 v = h4[(size_t)r * TPN + lane];
        acc.x += nm * v.x; acc.y += nm * v.y;
        acc.z += nm * v.z; acc.w += nm * v.w;
    }
    float4 b4 = ((const float4*)bias)[lane];
    acc.x += b4.x; acc.y += b4.y; acc.z += b4.z; acc.w += b4.w;
    ((float4*)out)[(size_t)node * TPN + lane] = acc;
}

// ---------------- adj = sigmoid(mu @ mu^T), tf32 tensor cores ----------------
__device__ __forceinline__ uint32_t f2tf(float f) {
    uint32_t u;
    asm("cvt.rna.tf32.f32 %0, %1;" : "=r"(u) : "f"(f));
    return u;
}

__device__ __forceinline__ float sigf(float x) {
    return __fdividef(1.f, 1.f + __expf(-x));
}

__device__ __forceinline__ void mma_tf32(float* d, const uint32_t* a, const uint32_t* b) {
    asm volatile(
        "mma.sync.aligned.m16n8k8.row.col.f32.tf32.tf32.f32 "
        "{%0,%1,%2,%3}, {%4,%5,%6,%7}, {%8,%9}, {%0,%1,%2,%3};"
        : "+f"(d[0]), "+f"(d[1]), "+f"(d[2]), "+f"(d[3])
        : "r"(a[0]), "r"(a[1]), "r"(a[2]), "r"(a[3]), "r"(b[0]), "r"(b[1]));
}

// 128x128 tile per block; 8 warps arranged 2(m) x 4(n); each warp 64x32
// (4 m-tiles of 16, 4 n-tiles of 8). Only bj>=bi tiles computed; mirror
// written directly (32B-sector coherent scalar stores).
__global__ __launch_bounds__(256, 2) void adj_tc_k(
    const float* __restrict__ mu, float* __restrict__ out)
{
    int bi = blockIdx.y, bj = blockIdx.x;
    if (bj < bi) return;
    __shared__ uint32_t As[128][36];   // [row][k], pad 36 => conflict-free frags
    __shared__ uint32_t Bs[128][36];
    int tid = threadIdx.x;
    int wid = tid >> 5, lane = tid & 31;
    int gid = lane >> 2, tig = lane & 3;
    int wm = (wid >> 2) * 64;          // warp m-offset (0 or 64)
    int wn = (wid & 3) * 32;           // warp n-offset (0,32,64,96)
    int r0 = bi * 128, c0 = bj * 128;

    float d[4][4][4];
    #pragma unroll
    for (int mt = 0; mt < 4; mt++)
        #pragma unroll
        for (int nt = 0; nt < 4; nt++)
            #pragma unroll
            for (int q = 0; q < 4; q++) d[mt][nt][q] = 0.f;

    for (int kc = 0; kc < LATD; kc += 32) {
        #pragma unroll
        for (int l = 0; l < 4; l++) {
            int idx = tid + l * 256;           // 0..1023
            int row = idx >> 3;                // 0..127
            int c4  = (idx & 7) * 4;           // 0..28
            float4 va = *(const float4*)&mu[(size_t)(r0 + row) * LATD + kc + c4];
            As[row][c4 + 0] = f2tf(va.x); As[row][c4 + 1] = f2tf(va.y);
            As[row][c4 + 2] = f2tf(va.z); As[row][c4 + 3] = f2tf(va.w);
            float4 vb = *(const float4*)&mu[(size_t)(c0 + row) * LATD + kc + c4];
            Bs[row][c4 + 0] = f2tf(vb.x); Bs[row][c4 + 1] = f2tf(vb.y);
            Bs[row][c4 + 2] = f2tf(vb.z); Bs[row][c4 + 3] = f2tf(vb.w);
        }
        __syncthreads();
        #pragma unroll
        for (int kk = 0; kk < 4; kk++) {
            int ka = kk * 8 + tig;
            uint32_t af[4][4], bf[4][2];
            #pragma unroll
            for (int mt = 0; mt < 4; mt++) {
                int r = wm + mt * 16 + gid;
                af[mt][0] = As[r][ka];     af[mt][1] = As[r + 8][ka];
                af[mt][2] = As[r][ka + 4]; af[mt][3] = As[r + 8][ka + 4];
            }
            #pragma unroll
            for (int nt = 0; nt < 4; nt++) {
                int cc = wn + nt * 8 + gid;
                bf[nt][0] = Bs[cc][ka];
                bf[nt][1] = Bs[cc][ka + 4];
            }
            #pragma unroll
            for (int mt = 0; mt < 4; mt++)
                #pragma unroll
                for (int nt = 0; nt < 4; nt++)
                    mma_tf32(d[mt][nt], af[mt], bf[nt]);
        }
        __syncthreads();
    }

    bool mirror = (bj > bi);
    #pragma unroll
    for (int mt = 0; mt < 4; mt++) {
        #pragma unroll
        for (int nt = 0; nt < 4; nt++) {
            int r = r0 + wm + mt * 16 + gid;
            int c = c0 + wn + nt * 8 + 2 * tig;
            float s0 = sigf(d[mt][nt][0]);
            float s1 = sigf(d[mt][nt][1]);
            float s2 = sigf(d[mt][nt][2]);
            float s3 = sigf(d[mt][nt][3]);
            float2 p0 = make_float2(s0, s1);
            float2 p1 = make_float2(s2, s3);
            *(float2*)&out[(size_t)r * NNODE + c]       = p0;
            *(float2*)&out[(size_t)(r + 8) * NNODE + c] = p1;
            if (mirror) {
                out[(size_t)c * NNODE + r]           = s0;
                out[(size_t)(c + 1) * NNODE + r]     = s1;
                out[(size_t)c * NNODE + r + 8]       = s2;
                out[(size_t)(c + 1) * NNODE + r + 8] = s3;
            }
        }
    }
}

// ---------------- launch -----------------------------------------------------
extern "C" void kernel_launch(void* const* d_in, const int* in_sizes, int n_in,
                              void* d_out, int out_size)
{
    const float* x   = (const float*)d_in[0];
    const void*  ei  = d_in[1];
    const float* W1  = (const float*)d_in[2];
    const float* b1  = (const float*)d_in[3];
    const float* W2  = (const float*)d_in[4];
    const float* b2  = (const float*)d_in[5];
    const float* Wmu = (const float*)d_in[6];
    const float* bmu = (const float*)d_in[7];
    const float* Wlv = (const float*)d_in[8];
    const float* blv = (const float*)d_in[9];

    float* out = (float*)d_out;                       // adj [N,N]
    float* mu  = out + (size_t)NNODE * NNODE;         // mu  [N,LAT]
    float* lv  = mu + (size_t)NNODE * LATD;           // logvar [N,LAT]

    float *d_h1, *d_z1, *d_h2, *d_z2;
    cudaGetSymbolAddress((void**)&d_h1, g_h1);
    cudaGetSymbolAddress((void**)&d_z1, g_z1);
    cudaGetSymbolAddress((void**)&d_h2, g_h2);
    cudaGetSymbolAddress((void**)&d_z2, g_z2);

    // graph structure
    detect_k<<<1, 256>>>((const int*)ei);
    zero_cnt_k<<<NNODE / 256, 256>>>();
    count_k<<<NEDGE / 256, 256>>>(ei);
    scan_k<<<1, 1024>>>();
    fill_k<<<NEDGE / 256, 256>>>(ei);

    // GCN layer 1: h1 = x @ W1 ; z1 = agg(h1) + b1
    sgemm128_k<false, false><<<dim3(H1D / 128, NNODE / 128), 256>>>(
        x, W1, nullptr, d_h1, NNODE, H1D, DIN);
    agg_k<H1D><<<NNODE / 4, 256>>>(d_h1, b1, d_z1);

    // GCN layer 2: h2 = relu(z1) @ W2 ; z2 = agg(h2) + b2
    sgemm128_k<true, false><<<dim3(LATD / 128, NNODE / 128), 256>>>(
        d_z1, W2, nullptr, d_h2, NNODE, LATD, H1D);
    agg_k<LATD><<<NNODE / 8, 256>>>(d_h2, b2, d_z2);

    // heads
    sgemm128_k<false, true><<<dim3(LATD / 128, NNODE / 128), 256>>>(
        d_z2, Wmu, bmu, mu, NNODE, LATD, LATD);
    sgemm128_k<false, true><<<dim3(LATD / 128, NNODE / 128), 256>>>(
        d_z2, Wlv, blv, lv, NNODE, LATD, LATD);

    // adj = sigmoid(mu @ mu^T), upper-triangle blocks + mirror
    adj_tc_k<<<dim3(NNODE / 128, NNODE / 128), 256>>>(mu, out);
}

// round 3
// speedup vs baseline: 1.7711x; 1.1756x over previous
#include <cuda_runtime.h>
#include <cstdint>

#define NNODE 8192
#define NEDGE 262144
#define DIN   512
#define H1D   256
#define LATD  128

// ---------------- scratch (device globals; no allocations allowed) ----------
__device__ int   g_cnt[NNODE];
__device__ int   g_start[NNODE + 1];
__device__ int   g_cursor[NNODE];
__device__ float g_dis[NNODE];
__device__ int   g_src[NEDGE];
__device__ float g_nrm[NEDGE];
__device__ float g_h1[NNODE * H1D];
__device__ float g_z1[NNODE * H1D];
__device__ float g_h2[NNODE * LATD];
__device__ float g_z2[NNODE * LATD];
__device__ int   g_is64;

// ---------------- init: zero counts + edge dtype detection ------------------
__global__ void init_k(const int* __restrict__ w) {
    int tid = threadIdx.x;
    g_cnt[blockIdx.x * 256 + tid] = 0;
    if (blockIdx.x == 0) {
        int z = (w[2 * tid + 1] == 0) ? 1 : 0;
        unsigned m = __ballot_sync(0xffffffffu, z);
        __shared__ int allz[8];
        if ((tid & 31) == 0) allz[tid >> 5] = (m == 0xffffffffu) ? 1 : 0;
        __syncthreads();
        if (tid == 0) {
            int a = 1;
            #pragma unroll
            for (int i = 0; i < 8; i++) a &= allz[i];
            g_is64 = a;
        }
    }
}

__device__ __forceinline__ int edge_at(const void* ei, int idx) {
    if (g_is64) return (int)((const long long*)ei)[idx];
    return ((const int*)ei)[idx];
}

__global__ void count_k(const void* __restrict__ ei) {
    int e = blockIdx.x * blockDim.x + threadIdx.x;
    if (e >= NEDGE) return;
    int c = edge_at(ei, NEDGE + e);
    atomicAdd(&g_cnt[c], 1);
}

// 256 threads, 32 elems each via int4 loads; also dis = (deg+2)^-1/2
__global__ void scan_k() {
    __shared__ int wsum[8];
    int t = threadIdx.x, lane = t & 31, w = t >> 5;
    const int4* c4 = (const int4*)g_cnt;
    int loc[32];
    int s = 0;
    #pragma unroll
    for (int i = 0; i < 8; i++) {
        int4 q = c4[t * 8 + i];
        loc[i * 4 + 0] = q.x; loc[i * 4 + 1] = q.y;
        loc[i * 4 + 2] = q.z; loc[i * 4 + 3] = q.w;
        s += q.x + q.y + q.z + q.w;
    }
    int v = s;
    #pragma unroll
    for (int off = 1; off < 32; off <<= 1) {
        int u = __shfl_up_sync(0xffffffffu, v, off);
        if (lane >= off) v += u;
    }
    if (lane == 31) wsum[w] = v;
    __syncthreads();
    if (t == 0) {
        int run = 0;
        #pragma unroll
        for (int i = 0; i < 8; i++) { int tmp = wsum[i]; wsum[i] = run; run += tmp; }
    }
    __syncthreads();
    int run = wsum[w] + (v - s);      // exclusive prefix
    #pragma unroll
    for (int i = 0; i < 32; i++) {
        int idx = t * 32 + i;
        g_start[idx]  = run;
        g_cursor[idx] = run;
        g_dis[idx] = rsqrtf((float)(loc[i] + 2));
        run += loc[i];
    }
    if (t == 255) g_start[NNODE] = run;
}

__global__ void fill_k(const void* __restrict__ ei) {
    int e = blockIdx.x * blockDim.x + threadIdx.x;
    if (e >= NEDGE) return;
    int r = edge_at(ei, e);
    int c = edge_at(ei, NEDGE + e);
    int p = atomicAdd(&g_cursor[c], 1);
    g_src[p] = r;
    g_nrm[p] = g_dis[r] * g_dis[c];
}

// ---------------- tf32 helpers ----------------------------------------------
__device__ __forceinline__ uint32_t f2tf(float f) {
    uint32_t u;
    asm("cvt.rna.tf32.f32 %0, %1;" : "=r"(u) : "f"(f));
    return u;
}

__device__ __forceinline__ void split_tf(float x, uint32_t& hi, uint32_t& lo) {
    hi = f2tf(x);
    lo = f2tf(x - __uint_as_float(hi));
}

__device__ __forceinline__ void mma_tf32(float* d, const uint32_t* a, const uint32_t* b) {
    asm volatile(
        "mma.sync.aligned.m16n8k8.row.col.f32.tf32.tf32.f32 "
        "{%0,%1,%2,%3}, {%4,%5,%6,%7}, {%8,%9}, {%0,%1,%2,%3};"
        : "+f"(d[0]), "+f"(d[1]), "+f"(d[2]), "+f"(d[3])
        : "r"(a[0]), "r"(a[1]), "r"(a[2]), "r"(a[3]), "r"(b[0]), "r"(b[1]));
}

// ---------------- split-tf32 GEMM (near-fp32 accuracy) -----------------------
// C[M,N] = op(A[M,K]) @ B[K,N] (+bias). Tile 128m x 64n, k-chunk 16.
// 8 warps: 4(m) x 2(n); warp tile 32x32 = mt2 x nt4 of m16n8.
// DUAL: grid.x = 2*halfTiles; second half uses B1/bias1/C1 (both N cols wide).
template <bool RELU_A, bool ADD_BIAS, bool DUAL>
__global__ __launch_bounds__(256) void tgemm_k(
    const float* __restrict__ A,
    const float* __restrict__ B0, const float* __restrict__ B1,
    const float* __restrict__ bias0, const float* __restrict__ bias1,
    float* __restrict__ C0, float* __restrict__ C1,
    int M, int N, int K, int halfTiles)
{
    const float* B = B0; const float* bias = bias0; float* C = C0;
    int bx = blockIdx.x;
    if (DUAL && bx >= halfTiles) { B = B1; bias = bias1; C = C1; bx -= halfTiles; }
    int r0 = blockIdx.y * 128, c0 = bx * 64;

    __shared__ uint32_t Ah[128][20], Al[128][20];
    __shared__ uint32_t Bh[16][68],  Bl[16][68];

    int tid = threadIdx.x;
    int wid = tid >> 5, lane = tid & 31;
    int gid = lane >> 2, tig = lane & 3;
    int wm = (wid >> 1) * 32;
    int wn = (wid & 1) * 32;

    float d[2][4][4];
    #pragma unroll
    for (int mt = 0; mt < 2; mt++)
        #pragma unroll
        for (int nt = 0; nt < 4; nt++)
            #pragma unroll
            for (int q = 0; q < 4; q++) d[mt][nt][q] = 0.f;

    for (int k0 = 0; k0 < K; k0 += 16) {
        #pragma unroll
        for (int l = 0; l < 2; l++) {
            int idx = tid + l * 256;            // 0..511
            int m  = idx >> 2;                  // 0..127
            int kc = (idx & 3) * 4;             // 0,4,8,12
            float4 v = *(const float4*)&A[(size_t)(r0 + m) * K + k0 + kc];
            if (RELU_A) {
                v.x = fmaxf(v.x, 0.f); v.y = fmaxf(v.y, 0.f);
                v.z = fmaxf(v.z, 0.f); v.w = fmaxf(v.w, 0.f);
            }
            uint4 h, o;
            split_tf(v.x, h.x, o.x); split_tf(v.y, h.y, o.y);
            split_tf(v.z, h.z, o.z); split_tf(v.w, h.w, o.w);
            *(uint4*)&Ah[m][kc] = h;
            *(uint4*)&Al[m][kc] = o;
        }
        {
            int kb = tid >> 4;                  // 0..15
            int nb = (tid & 15) * 4;            // 0..60
            float4 v = *(const float4*)&B[(size_t)(k0 + kb) * N + c0 + nb];
            uint4 h, o;
            split_tf(v.x, h.x, o.x); split_tf(v.y, h.y, o.y);
            split_tf(v.z, h.z, o.z); split_tf(v.w, h.w, o.w);
            *(uint4*)&Bh[kb][nb] = h;
            *(uint4*)&Bl[kb][nb] = o;
        }
        __syncthreads();
        #pragma unroll
        for (int kk = 0; kk < 2; kk++) {
            int ka = kk * 8 + tig;
            uint32_t ah[2][4], al[2][4], bh[4][2], bl[4][2];
            #pragma unroll
            for (int mt = 0; mt < 2; mt++) {
                int r = wm + mt * 16 + gid;
                ah[mt][0] = Ah[r][ka];     ah[mt][1] = Ah[r + 8][ka];
                ah[mt][2] = Ah[r][ka + 4]; ah[mt][3] = Ah[r + 8][ka + 4];
                al[mt][0] = Al[r][ka];     al[mt][1] = Al[r + 8][ka];
                al[mt][2] = Al[r][ka + 4]; al[mt][3] = Al[r + 8][ka + 4];
            }
            #pragma unroll
            for (int nt = 0; nt < 4; nt++) {
                int c = wn + nt * 8 + gid;
                bh[nt][0] = Bh[ka][c]; bh[nt][1] = Bh[ka + 4][c];
                bl[nt][0] = Bl[ka][c]; bl[nt][1] = Bl[ka + 4][c];
            }
            #pragma unroll
            for (int mt = 0; mt < 2; mt++)
                #pragma unroll
                for (int nt = 0; nt < 4; nt++) {
                    mma_tf32(d[mt][nt], ah[mt], bh[nt]);
                    mma_tf32(d[mt][nt], al[mt], bh[nt]);
                    mma_tf32(d[mt][nt], ah[mt], bl[nt]);
                }
        }
        __syncthreads();
    }

    #pragma unroll
    for (int mt = 0; mt < 2; mt++) {
        #pragma unroll
        for (int nt = 0; nt < 4; nt++) {
            int r = r0 + wm + mt * 16 + gid;
            int c = c0 + wn + nt * 8 + 2 * tig;
            float b0 = 0.f, b1 = 0.f;
            if (ADD_BIAS) { b0 = bias[c]; b1 = bias[c + 1]; }
            float2 p0 = make_float2(d[mt][nt][0] + b0, d[mt][nt][1] + b1);
            float2 p1 = make_float2(d[mt][nt][2] + b0, d[mt][nt][3] + b1);
            *(float2*)&C[(size_t)r * N + c]       = p0;
            *(float2*)&C[(size_t)(r + 8) * N + c] = p1;
        }
    }
}

// ---------------- CSR aggregation (no atomics) -------------------------------
template <int D>
__global__ __launch_bounds__(256) void agg_k(
    const float* __restrict__ h, const float* __restrict__ bias,
    float* __restrict__ out)
{
    const int TPN = D / 4;
    const int NPB = 256 / TPN;
    int node = blockIdx.x * NPB + threadIdx.x / TPN;
    int lane = threadIdx.x % TPN;
    const float4* h4 = (const float4*)h;

    int s = g_start[node];
    int e = g_start[node + 1];
    float dv = g_dis[node];
    float self = 2.f * dv * dv;

    float4 hv = h4[(size_t)node * TPN + lane];
    float4 acc;
    acc.x = hv.x * self; acc.y = hv.y * self;
    acc.z = hv.z * self; acc.w = hv.w * self;

    for (int i = s; i < e; i++) {
        int r = g_src[i];
        float nm = g_nrm[i];
        float4 v = h4[(size_t)r * TPN + lane];
        acc.x += nm * v.x; acc.y += nm * v.y;
        acc.z += nm * v.z; acc.w += nm * v.w;
    }
    float4 b4 = ((const float4*)bias)[lane];
    acc.x += b4.x; acc.y += b4.y; acc.z += b4.z; acc.w += b4.w;
    ((float4*)out)[(size_t)node * TPN + lane] = acc;
}

// ---------------- adj = sigmoid(mu @ mu^T), tf32, triangular grid ------------
__device__ __forceinline__ float sigf(float x) {
    return __fdividef(1.f, 1.f + __expf(-x));
}

__device__ __forceinline__ int tri_cum(int bi) {   // tiles before row bi (NB=64)
    return bi * 64 - (bi * (bi - 1)) / 2;
}

__global__ __launch_bounds__(256, 2) void adj_tc_k(
    const float* __restrict__ mu, float* __restrict__ out)
{
    // map 1D block id -> upper-triangular (bi, bj), bj >= bi
    int k = blockIdx.x;
    int bi = (int)floorf(64.5f - sqrtf(64.5f * 64.5f - 2.0f * (float)k));
    while (tri_cum(bi + 1) <= k) bi++;
    while (tri_cum(bi) > k) bi--;
    int bj = bi + (k - tri_cum(bi));

    __shared__ uint32_t As[128][36];
    __shared__ uint32_t Bs[128][36];
    int tid = threadIdx.x;
    int wid = tid >> 5, lane = tid & 31;
    int gid = lane >> 2, tig = lane & 3;
    int wm = (wid >> 2) * 64;
    int wn = (wid & 3) * 32;
    int r0 = bi * 128, c0 = bj * 128;

    float d[4][4][4];
    #pragma unroll
    for (int mt = 0; mt < 4; mt++)
        #pragma unroll
        for (int nt = 0; nt < 4; nt++)
            #pragma unroll
            for (int q = 0; q < 4; q++) d[mt][nt][q] = 0.f;

    for (int kc = 0; kc < LATD; kc += 32) {
        #pragma unroll
        for (int l = 0; l < 4; l++) {
            int idx = tid + l * 256;
            int row = idx >> 3;
            int c4  = (idx & 7) * 4;
            float4 va = *(const float4*)&mu[(size_t)(r0 + row) * LATD + kc + c4];
            As[row][c4 + 0] = f2tf(va.x); As[row][c4 + 1] = f2tf(va.y);
            As[row][c4 + 2] = f2tf(va.z); As[row][c4 + 3] = f2tf(va.w);
            float4 vb = *(const float4*)&mu[(size_t)(c0 + row) * LATD + kc + c4];
            Bs[row][c4 + 0] = f2tf(vb.x); Bs[row][c4 + 1] = f2tf(vb.y);
            Bs[row][c4 + 2] = f2tf(vb.z); Bs[row][c4 + 3] = f2tf(vb.w);
        }
        __syncthreads();
        #pragma unroll
        for (int kk = 0; kk < 4; kk++) {
            int ka = kk * 8 + tig;
            uint32_t af[4][4], bf[4][2];
            #pragma unroll
            for (int mt = 0; mt < 4; mt++) {
                int r = wm + mt * 16 + gid;
                af[mt][0] = As[r][ka];     af[mt][1] = As[r + 8][ka];
                af[mt][2] = As[r][ka + 4]; af[mt][3] = As[r + 8][ka + 4];
            }
            #pragma unroll
            for (int nt = 0; nt < 4; nt++) {
                int cc = wn + nt * 8 + gid;
                bf[nt][0] = Bs[cc][ka];
                bf[nt][1] = Bs[cc][ka + 4];
            }
            #pragma unroll
            for (int mt = 0; mt < 4; mt++)
                #pragma unroll
                for (int nt = 0; nt < 4; nt++)
                    mma_tf32(d[mt][nt], af[mt], bf[nt]);
        }
        __syncthreads();
    }

    bool mirror = (bj > bi);
    #pragma unroll
    for (int mt = 0; mt < 4; mt++) {
        #pragma unroll
        for (int nt = 0; nt < 4; nt++) {
            int r = r0 + wm + mt * 16 + gid;
            int c = c0 + wn + nt * 8 + 2 * tig;
            float s0 = sigf(d[mt][nt][0]);
            float s1 = sigf(d[mt][nt][1]);
            float s2 = sigf(d[mt][nt][2]);
            float s3 = sigf(d[mt][nt][3]);
            *(float2*)&out[(size_t)r * NNODE + c]       = make_float2(s0, s1);
            *(float2*)&out[(size_t)(r + 8) * NNODE + c] = make_float2(s2, s3);
            if (mirror) {
                out[(size_t)c * NNODE + r]           = s0;
                out[(size_t)(c + 1) * NNODE + r]     = s1;
                out[(size_t)c * NNODE + r + 8]       = s2;
                out[(size_t)(c + 1) * NNODE + r + 8] = s3;
            }
        }
    }
}

// ---------------- launch -----------------------------------------------------
extern "C" void kernel_launch(void* const* d_in, const int* in_sizes, int n_in,
                              void* d_out, int out_size)
{
    const float* x   = (const float*)d_in[0];
    const void*  ei  = d_in[1];
    const float* W1  = (const float*)d_in[2];
    const float* b1  = (const float*)d_in[3];
    const float* W2  = (const float*)d_in[4];
    const float* b2  = (const float*)d_in[5];
    const float* Wmu = (const float*)d_in[6];
    const float* bmu = (const float*)d_in[7];
    const float* Wlv = (const float*)d_in[8];
    const float* blv = (const float*)d_in[9];

    float* out = (float*)d_out;                       // adj [N,N]
    float* mu  = out + (size_t)NNODE * NNODE;         // mu  [N,LAT]
    float* lv  = mu + (size_t)NNODE * LATD;           // logvar [N,LAT]

    float *d_h1, *d_z1, *d_h2, *d_z2;
    cudaGetSymbolAddress((void**)&d_h1, g_h1);
    cudaGetSymbolAddress((void**)&d_z1, g_z1);
    cudaGetSymbolAddress((void**)&d_h2, g_h2);
    cudaGetSymbolAddress((void**)&d_z2, g_z2);

    // graph structure
    init_k<<<NNODE / 256, 256>>>((const int*)ei);
    count_k<<<NEDGE / 256, 256>>>(ei);
    scan_k<<<1, 256>>>();
    fill_k<<<NEDGE / 256, 256>>>(ei);

    // GCN layer 1: h1 = x @ W1 ; z1 = agg(h1) + b1
    tgemm_k<false, false, false><<<dim3(H1D / 64, NNODE / 128), 256>>>(
        x, W1, nullptr, nullptr, nullptr, d_h1, nullptr, NNODE, H1D, DIN, 0);
    agg_k<H1D><<<NNODE / 4, 256>>>(d_h1, b1, d_z1);

    // GCN layer 2: h2 = relu(z1) @ W2 ; z2 = agg(h2) + b2
    tgemm_k<true, false, false><<<dim3(LATD / 64, NNODE / 128), 256>>>(
        d_z1, W2, nullptr, nullptr, nullptr, d_h2, nullptr, NNODE, LATD, H1D, 0);
    agg_k<LATD><<<NNODE / 8, 256>>>(d_h2, b2, d_z2);

    // heads: mu and logvar fused in one launch (grid.x = 4 = 2 outputs x 2 tiles)
    tgemm_k<false, true, true><<<dim3(4, NNODE / 128), 256>>>(
        d_z2, Wmu, Wlv, bmu, blv, mu, lv, NNODE, LATD, LATD, 2);

    // adj = sigmoid(mu @ mu^T), upper-triangle blocks + mirror
    adj_tc_k<<<2080, 256>>>(mu, out);
}

// round 4
// speedup vs baseline: 1.9003x; 1.0729x over previous
#include <cuda_runtime.h>
#include <cstdint>

#define NNODE 8192
#define NEDGE 262144
#define DIN   512
#define H1D   256
#define LATD  128

// ---------------- scratch (device globals; no allocations allowed) ----------
__device__ int   g_cnt[NNODE];          // zero at module load; re-zeroed by scan_k
__device__ int   g_start[NNODE + 1];
__device__ int   g_cursor[NNODE];
__device__ float g_dis[NNODE];
__device__ int   g_src[NEDGE];
__device__ float g_nrm[NEDGE];
__device__ float g_h1[NNODE * H1D];
__device__ float g_z1[NNODE * H1D];
__device__ float g_h2[NNODE * LATD];
__device__ float g_z2[NNODE * LATD];

// ---------------- cp.async helpers ------------------------------------------
__device__ __forceinline__ void cp16(uint32_t dst, const void* src) {
    asm volatile("cp.async.ca.shared.global [%0], [%1], 16;" :: "r"(dst), "l"(src));
}
__device__ __forceinline__ void cp_commit() {
    asm volatile("cp.async.commit_group;");
}
template <int N>
__device__ __forceinline__ void cp_wait() {
    asm volatile("cp.async.wait_group %0;" :: "n"(N));
}

// ---------------- per-block edge dtype detection ------------------------------
// int64 little-endian node ids < 8192 => odd 32-bit words of first 512 are 0.
__device__ __forceinline__ int detect_is64(const int* w) {
    __shared__ int allz[8];
    __shared__ int s64;
    int tid = threadIdx.x;
    if (tid < 256) {
        int z = (w[2 * tid + 1] == 0) ? 1 : 0;
        unsigned m = __ballot_sync(0xffffffffu, z);
        if ((tid & 31) == 0) allz[tid >> 5] = (m == 0xffffffffu) ? 1 : 0;
    }
    __syncthreads();
    if (tid == 0) {
        int a = 1;
        #pragma unroll
        for (int i = 0; i < 8; i++) a &= allz[i];
        s64 = a;
    }
    __syncthreads();
    return s64;
}

__global__ void count_k(const void* __restrict__ ei) {
    int is64 = detect_is64((const int*)ei);
    int e = blockIdx.x * 256 + threadIdx.x;
    int c = is64 ? (int)((const long long*)ei)[NEDGE + e]
                 : ((const int*)ei)[NEDGE + e];
    atomicAdd(&g_cnt[c], 1);
}

// 256 threads, 32 elems each via int4; also dis = (deg+2)^-1/2; re-zeros g_cnt
__global__ void scan_k() {
    __shared__ int wsum[8];
    int t = threadIdx.x, lane = t & 31, w = t >> 5;
    int4* c4 = (int4*)g_cnt;
    int loc[32];
    int s = 0;
    #pragma unroll
    for (int i = 0; i < 8; i++) {
        int4 q = c4[t * 8 + i];
        loc[i * 4 + 0] = q.x; loc[i * 4 + 1] = q.y;
        loc[i * 4 + 2] = q.z; loc[i * 4 + 3] = q.w;
        s += q.x + q.y + q.z + q.w;
        c4[t * 8 + i] = make_int4(0, 0, 0, 0);   // ready for next replay
    }
    int v = s;
    #pragma unroll
    for (int off = 1; off < 32; off <<= 1) {
        int u = __shfl_up_sync(0xffffffffu, v, off);
        if (lane >= off) v += u;
    }
    if (lane == 31) wsum[w] = v;
    __syncthreads();
    if (t == 0) {
        int run = 0;
        #pragma unroll
        for (int i = 0; i < 8; i++) { int tmp = wsum[i]; wsum[i] = run; run += tmp; }
    }
    __syncthreads();
    int run = wsum[w] + (v - s);
    #pragma unroll
    for (int i = 0; i < 32; i++) {
        int idx = t * 32 + i;
        g_start[idx]  = run;
        g_cursor[idx] = run;
        g_dis[idx] = rsqrtf((float)(loc[i] + 2));
        run += loc[i];
    }
    if (t == 255) g_start[NNODE] = run;
}

__global__ void fill_k(const void* __restrict__ ei) {
    int is64 = detect_is64((const int*)ei);
    int e = blockIdx.x * 256 + threadIdx.x;
    int r, c;
    if (is64) {
        r = (int)((const long long*)ei)[e];
        c = (int)((const long long*)ei)[NEDGE + e];
    } else {
        r = ((const int*)ei)[e];
        c = ((const int*)ei)[NEDGE + e];
    }
    int p = atomicAdd(&g_cursor[c], 1);
    g_src[p] = r;
    g_nrm[p] = g_dis[r] * g_dis[c];
}

// ---------------- tf32 helpers ----------------------------------------------
__device__ __forceinline__ uint32_t f2tf(float f) {
    uint32_t u;
    asm("cvt.rna.tf32.f32 %0, %1;" : "=r"(u) : "f"(f));
    return u;
}
__device__ __forceinline__ void split_tf(float x, uint32_t& hi, uint32_t& lo) {
    hi = f2tf(x);
    lo = f2tf(x - __uint_as_float(hi));
}
__device__ __forceinline__ void mma_tf32(float* d, const uint32_t* a, const uint32_t* b) {
    asm volatile(
        "mma.sync.aligned.m16n8k8.row.col.f32.tf32.tf32.f32 "
        "{%0,%1,%2,%3}, {%4,%5,%6,%7}, {%8,%9}, {%0,%1,%2,%3};"
        : "+f"(d[0]), "+f"(d[1]), "+f"(d[2]), "+f"(d[3])
        : "r"(a[0]), "r"(a[1]), "r"(a[2]), "r"(a[3]), "r"(b[0]), "r"(b[1]));
}

// ---------------- split-tf32 GEMM, reg-prefetch pipeline ---------------------
// C[M,N] = A[M,K] @ B[K,N] (+bias). Tile 128m x 64n, k-chunk 16.
// 8 warps 4(m) x 2(n); warp tile 32x32 = 2x4 of m16n8.
template <bool ADD_BIAS, bool DUAL>
__global__ __launch_bounds__(256) void tgemm_k(
    const float* __restrict__ A,
    const float* __restrict__ B0, const float* __restrict__ B1,
    const float* __restrict__ bias0, const float* __restrict__ bias1,
    float* __restrict__ C0, float* __restrict__ C1,
    int M, int N, int K, int halfTiles)
{
    const float* B = B0; const float* bias = bias0; float* C = C0;
    int bx = blockIdx.x;
    if (DUAL && bx >= halfTiles) { B = B1; bias = bias1; C = C1; bx -= halfTiles; }
    int r0 = blockIdx.y * 128, c0 = bx * 64;

    __shared__ uint32_t Ah[128][20], Al[128][20];
    __shared__ uint32_t Bh[16][68],  Bl[16][68];

    int tid = threadIdx.x;
    int wid = tid >> 5, lane = tid & 31;
    int gid = lane >> 2, tig = lane & 3;
    int wm = (wid >> 1) * 32;
    int wn = (wid & 1) * 32;

    // per-thread load coords (fixed across chunks)
    int am0 = tid >> 2,         akc = (tid & 3) * 4;        // l=0
    int am1 = (tid + 256) >> 2;                              // l=1 (same akc)
    int bkb = tid >> 4,         bnb = (tid & 15) * 4;

    const float* pA0 = &A[(size_t)(r0 + am0) * K + akc];
    const float* pA1 = &A[(size_t)(r0 + am1) * K + akc];
    const float* pB  = &B[(size_t)bkb * N + c0 + bnb];

    float d[2][4][4];
    #pragma unroll
    for (int mt = 0; mt < 2; mt++)
        #pragma unroll
        for (int nt = 0; nt < 4; nt++)
            #pragma unroll
            for (int q = 0; q < 4; q++) d[mt][nt][q] = 0.f;

    float4 a0 = *(const float4*)pA0;
    float4 a1 = *(const float4*)pA1;
    float4 b0 = *(const float4*)pB;

    for (int k0 = 0; k0 < K; k0 += 16) {
        {   // split & stage current chunk
            uint4 h, o;
            split_tf(a0.x, h.x, o.x); split_tf(a0.y, h.y, o.y);
            split_tf(a0.z, h.z, o.z); split_tf(a0.w, h.w, o.w);
            *(uint4*)&Ah[am0][akc] = h; *(uint4*)&Al[am0][akc] = o;
            split_tf(a1.x, h.x, o.x); split_tf(a1.y, h.y, o.y);
            split_tf(a1.z, h.z, o.z); split_tf(a1.w, h.w, o.w);
            *(uint4*)&Ah[am1][akc] = h; *(uint4*)&Al[am1][akc] = o;
            split_tf(b0.x, h.x, o.x); split_tf(b0.y, h.y, o.y);
            split_tf(b0.z, h.z, o.z); split_tf(b0.w, h.w, o.w);
            *(uint4*)&Bh[bkb][bnb] = h; *(uint4*)&Bl[bkb][bnb] = o;
        }
        __syncthreads();
        if (k0 + 16 < K) {   // prefetch next chunk (latency overlaps mma)
            a0 = *(const float4*)(pA0 + k0 + 16);
            a1 = *(const float4*)(pA1 + k0 + 16);
            b0 = *(const float4*)(pB + (size_t)16 * N + (size_t)k0 * N / 16 * 0);
            b0 = *(const float4*)&B[(size_t)(k0 + 16 + bkb) * N + c0 + bnb];
        }
        #pragma unroll
        for (int kk = 0; kk < 2; kk++) {
            int ka = kk * 8 + tig;
            uint32_t ah[2][4], al[2][4], bh[4][2], bl[4][2];
            #pragma unroll
            for (int mt = 0; mt < 2; mt++) {
                int r = wm + mt * 16 + gid;
                ah[mt][0] = Ah[r][ka];     ah[mt][1] = Ah[r + 8][ka];
                ah[mt][2] = Ah[r][ka + 4]; ah[mt][3] = Ah[r + 8][ka + 4];
                al[mt][0] = Al[r][ka];     al[mt][1] = Al[r + 8][ka];
                al[mt][2] = Al[r][ka + 4]; al[mt][3] = Al[r + 8][ka + 4];
            }
            #pragma unroll
            for (int nt = 0; nt < 4; nt++) {
                int c = wn + nt * 8 + gid;
                bh[nt][0] = Bh[ka][c]; bh[nt][1] = Bh[ka + 4][c];
                bl[nt][0] = Bl[ka][c]; bl[nt][1] = Bl[ka + 4][c];
            }
            #pragma unroll
            for (int mt = 0; mt < 2; mt++)
                #pragma unroll
                for (int nt = 0; nt < 4; nt++) {
                    mma_tf32(d[mt][nt], ah[mt], bh[nt]);
                    mma_tf32(d[mt][nt], al[mt], bh[nt]);
                    mma_tf32(d[mt][nt], ah[mt], bl[nt]);
                }
        }
        __syncthreads();
    }

    #pragma unroll
    for (int mt = 0; mt < 2; mt++) {
        #pragma unroll
        for (int nt = 0; nt < 4; nt++) {
            int r = r0 + wm + mt * 16 + gid;
            int c = c0 + wn + nt * 8 + 2 * tig;
            float bb0 = 0.f, bb1 = 0.f;
            if (ADD_BIAS) { bb0 = bias[c]; bb1 = bias[c + 1]; }
            *(float2*)&C[(size_t)r * N + c] =
                make_float2(d[mt][nt][0] + bb0, d[mt][nt][1] + bb1);
            *(float2*)&C[(size_t)(r + 8) * N + c] =
                make_float2(d[mt][nt][2] + bb0, d[mt][nt][3] + bb1);
        }
    }
}

// ---------------- CSR aggregation (no atomics) -------------------------------
template <int D, bool RELU_OUT>
__global__ __launch_bounds__(256) void agg_k(
    const float* __restrict__ h, const float* __restrict__ bias,
    float* __restrict__ out)
{
    const int TPN = D / 4;
    const int NPB = 256 / TPN;
    int node = blockIdx.x * NPB + threadIdx.x / TPN;
    int lane = threadIdx.x % TPN;
    const float4* h4 = (const float4*)h;

    int s = g_start[node];
    int e = g_start[node + 1];
    float dv = g_dis[node];
    float self = 2.f * dv * dv;

    float4 hv = h4[(size_t)node * TPN + lane];
    float4 acc;
    acc.x = hv.x * self; acc.y = hv.y * self;
    acc.z = hv.z * self; acc.w = hv.w * self;

    for (int i = s; i < e; i++) {
        int r = g_src[i];
        float nm = g_nrm[i];
        float4 v = h4[(size_t)r * TPN + lane];
        acc.x += nm * v.x; acc.y += nm * v.y;
        acc.z += nm * v.z; acc.w += nm * v.w;
    }
    float4 b4 = ((const float4*)bias)[lane];
    acc.x += b4.x; acc.y += b4.y; acc.z += b4.z; acc.w += b4.w;
    if (RELU_OUT) {
        acc.x = fmaxf(acc.x, 0.f); acc.y = fmaxf(acc.y, 0.f);
        acc.z = fmaxf(acc.z, 0.f); acc.w = fmaxf(acc.w, 0.f);
    }
    ((float4*)out)[(size_t)node * TPN + lane] = acc;
}

// ---------------- adj = sigmoid(mu @ mu^T), tf32 + cp.async pipeline ---------
__device__ __forceinline__ float sigf(float x) {
    return __fdividef(1.f, 1.f + __expf(-x));
}
__device__ __forceinline__ int tri_cum(int bi) {
    return bi * 64 - (bi * (bi - 1)) / 2;
}

#define ADJ_STG 9216   // words per stage: 2 tiles x 128 x 36

__global__ __launch_bounds__(256, 2) void adj_tc_k(
    const float* __restrict__ mu, float* __restrict__ out)
{
    extern __shared__ uint32_t dyn[];
    int k = blockIdx.x;
    int bi = (int)floorf(64.5f - sqrtf(64.5f * 64.5f - 2.0f * (float)k));
    while (tri_cum(bi + 1) <= k) bi++;
    while (tri_cum(bi) > k) bi--;
    int bj = bi + (k - tri_cum(bi));

    int tid = threadIdx.x;
    int wid = tid >> 5, lane = tid & 31;
    int gid = lane >> 2, tig = lane & 3;
    int wm = (wid >> 2) * 64;
    int wn = (wid & 3) * 32;
    int r0 = bi * 128, c0 = bj * 128;

    uint32_t sbase = (uint32_t)__cvta_generic_to_shared(dyn);
    // per-thread copy coords
    int crow = tid >> 3;            // +l*32 per segment
    int cc4  = (tid & 7) * 4;

    // issue chunk 0
    {
        uint32_t base = sbase;
        #pragma unroll
        for (int l = 0; l < 4; l++) {
            int row = crow + l * 32;
            cp16(base + (uint32_t)(row * 36 + cc4) * 4,
                 &mu[(size_t)(r0 + row) * LATD + cc4]);
            cp16(base + (uint32_t)(4608 + row * 36 + cc4) * 4,
                 &mu[(size_t)(c0 + row) * LATD + cc4]);
        }
        cp_commit();
    }

    float d[4][4][4];
    #pragma unroll
    for (int mt = 0; mt < 4; mt++)
        #pragma unroll
        for (int nt = 0; nt < 4; nt++)
            #pragma unroll
            for (int q = 0; q < 4; q++) d[mt][nt][q] = 0.f;

    #pragma unroll
    for (int c = 0; c < 4; c++) {
        if (c < 3) {   // prefetch chunk c+1 into other stage
            uint32_t base = sbase + ((c + 1) & 1) * ADJ_STG * 4;
            int kc = (c + 1) * 32;
            #pragma unroll
            for (int l = 0; l < 4; l++) {
                int row = crow + l * 32;
                cp16(base + (uint32_t)(row * 36 + cc4) * 4,
                     &mu[(size_t)(r0 + row) * LATD + kc + cc4]);
                cp16(base + (uint32_t)(4608 + row * 36 + cc4) * 4,
                     &mu[(size_t)(c0 + row) * LATD + kc + cc4]);
            }
            cp_commit();
            cp_wait<1>();
        } else {
            cp_wait<0>();
        }
        __syncthreads();

        const uint32_t* As = dyn + (c & 1) * ADJ_STG;
        const uint32_t* Bs = As + 4608;
        #pragma unroll
        for (int kk = 0; kk < 4; kk++) {
            int ka = kk * 8 + tig;
            uint32_t af[4][4], bf[4][2];
            #pragma unroll
            for (int mt = 0; mt < 4; mt++) {
                int r = wm + mt * 16 + gid;
                af[mt][0] = As[r * 36 + ka];         af[mt][1] = As[(r + 8) * 36 + ka];
                af[mt][2] = As[r * 36 + ka + 4];     af[mt][3] = As[(r + 8) * 36 + ka + 4];
            }
            #pragma unroll
            for (int nt = 0; nt < 4; nt++) {
                int cc = wn + nt * 8 + gid;
                bf[nt][0] = Bs[cc * 36 + ka];
                bf[nt][1] = Bs[cc * 36 + ka + 4];
            }
            #pragma unroll
            for (int mt = 0; mt < 4; mt++)
                #pragma unroll
                for (int nt = 0; nt < 4; nt++)
                    mma_tf32(d[mt][nt], af[mt], bf[nt]);
        }
        __syncthreads();
    }

    bool mirror = (bj > bi);
    #pragma unroll
    for (int mt = 0; mt < 4; mt++) {
        #pragma unroll
        for (int nt = 0; nt < 4; nt++) {
            int r = r0 + wm + mt * 16 + gid;
            int c = c0 + wn + nt * 8 + 2 * tig;
            float s0 = sigf(d[mt][nt][0]);
            float s1 = sigf(d[mt][nt][1]);
            float s2 = sigf(d[mt][nt][2]);
            float s3 = sigf(d[mt][nt][3]);
            *(float2*)&out[(size_t)r * NNODE + c]       = make_float2(s0, s1);
            *(float2*)&out[(size_t)(r + 8) * NNODE + c] = make_float2(s2, s3);
            if (mirror) {
                out[(size_t)c * NNODE + r]           = s0;
                out[(size_t)(c + 1) * NNODE + r]     = s1;
                out[(size_t)c * NNODE + r + 8]       = s2;
                out[(size_t)(c + 1) * NNODE + r + 8] = s3;
            }
        }
    }
}

// ---------------- launch -----------------------------------------------------
extern "C" void kernel_launch(void* const* d_in, const int* in_sizes, int n_in,
                              void* d_out, int out_size)
{
    const float* x   = (const float*)d_in[0];
    const void*  ei  = d_in[1];
    const float* W1  = (const float*)d_in[2];
    const float* b1  = (const float*)d_in[3];
    const float* W2  = (const float*)d_in[4];
    const float* b2  = (const float*)d_in[5];
    const float* Wmu = (const float*)d_in[6];
    const float* bmu = (const float*)d_in[7];
    const float* Wlv = (const float*)d_in[8];
    const float* blv = (const float*)d_in[9];

    float* out = (float*)d_out;                       // adj [N,N]
    float* mu  = out + (size_t)NNODE * NNODE;         // mu  [N,LAT]
    float* lv  = mu + (size_t)NNODE * LATD;           // logvar [N,LAT]

    float *d_h1, *d_z1, *d_h2, *d_z2;
    cudaGetSymbolAddress((void**)&d_h1, g_h1);
    cudaGetSymbolAddress((void**)&d_z1, g_z1);
    cudaGetSymbolAddress((void**)&d_h2, g_h2);
    cudaGetSymbolAddress((void**)&d_z2, g_z2);

    static int smem_set = 0;
    if (!smem_set) {
        cudaFuncSetAttribute(adj_tc_k,
            cudaFuncAttributeMaxDynamicSharedMemorySize, 2 * ADJ_STG * 4);
        smem_set = 1;
    }

    // graph structure (g_cnt is zero on entry; scan_k re-zeroes it)
    count_k<<<NEDGE / 256, 256>>>(ei);
    scan_k<<<1, 256>>>();
    fill_k<<<NEDGE / 256, 256>>>(ei);

    // GCN layer 1: h1 = x @ W1 ; z1 = relu(agg(h1) + b1)
    tgemm_k<false, false><<<dim3(H1D / 64, NNODE / 128), 256>>>(
        x, W1, nullptr, nullptr, nullptr, d_h1, nullptr, NNODE, H1D, DIN, 0);
    agg_k<H1D, true><<<NNODE / 4, 256>>>(d_h1, b1, d_z1);

    // GCN layer 2: h2 = z1 @ W2 ; z2 = agg(h2) + b2
    tgemm_k<false, false><<<dim3(LATD / 64, NNODE / 128), 256>>>(
        d_z1, W2, nullptr, nullptr, nullptr, d_h2, nullptr, NNODE, LATD, H1D, 0);
    agg_k<LATD, false><<<NNODE / 8, 256>>>(d_h2, b2, d_z2);

    // heads: mu and logvar fused (grid.x = 4 = 2 outputs x 2 col-tiles)
    tgemm_k<true, true><<<dim3(4, NNODE / 128), 256>>>(
        d_z2, Wmu, Wlv, bmu, blv, mu, lv, NNODE, LATD, LATD, 2);

    // adj = sigmoid(mu @ mu^T), upper-triangle + mirror
    adj_tc_k<<<2080, 256, 2 * ADJ_STG * 4>>>(mu, out);
}